// round 3
// baseline (speedup 1.0000x reference)
#include <cuda_runtime.h>

// QORNN: B=256, T=1024, I=64, H=256, O=16
// Exact integer formulation:
//   xq  = clip(rint(x*128), -128, 127)              (int8)
//   wiq = clip(rint(Wi*8),  -8, 7)                  (int4-in-int8)
//   wrq = clip(rint(Wr*8),  -8, 7)
//   woq = clip(rint(Wo*8),  -8, 7)
//   u_int[b,t,j] = sum_i xq*wiq                     (int32, |.|<=65536)
//   z_int = u_int + sum_k hq*wrq                    (|.|<=327680 < 2^24 -> fp32-exact)
//   m = max(|z_int|/1024 + b[j], 0)
//   hq = sign(z_int) * clip(rint(m*128), ..)        in [-128,127]
//   out[b,o] = (sum_j hq*woq) / 1024
// All fp32 roundings match the JAX reference bit-exactly (rint = half-even,
// scaling by powers of two is exact and commutes with rounding).

#define BB 256
#define TT 1024
#define II 64
#define HH 256
#define OO 16

// Scratch (allocation-free rule: __device__ globals)
__device__ int d_u[BB * TT * HH];   // 268 MB int32, u numerators
__device__ int d_wr4[64 * HH];      // [q][j]: packed wrq[j][4q..4q+3]
__device__ int d_wi4[16 * HH];      // [q][j]: packed wiq[j][4q..4q+3]
__device__ int d_wo4[OO * 64];      // [o][q]: packed woq[o][4q..4q+3]

__device__ __forceinline__ int clampi(int v, int lo, int hi) {
    return v < lo ? lo : (v > hi ? hi : v);
}

// Quantize 4 floats (round-half-even, clip) and pack into one dp4a word.
__device__ __forceinline__ int qpack4(float4 v, float s, int lo, int hi) {
    int a = clampi(__float2int_rn(v.x * s), lo, hi);
    int b = clampi(__float2int_rn(v.y * s), lo, hi);
    int c = clampi(__float2int_rn(v.z * s), lo, hi);
    int d = clampi(__float2int_rn(v.w * s), lo, hi);
    return (a & 255) | ((b & 255) << 8) | ((c & 255) << 16) | ((d & 255) << 24);
}

// ---------------------------------------------------------------------------
// Kernel 1: quantize + pack all weights (tiny)
// ---------------------------------------------------------------------------
__global__ void pack_weights_kernel(const float* __restrict__ Wi,
                                    const float* __restrict__ Wr,
                                    const float* __restrict__ Wo) {
    int j = threadIdx.x;  // 0..255
    const float4* wr = (const float4*)(Wr + j * HH);
#pragma unroll
    for (int q = 0; q < 64; q++)
        d_wr4[q * HH + j] = qpack4(wr[q], 8.0f, -8, 7);
    const float4* wi = (const float4*)(Wi + j * II);
#pragma unroll
    for (int q = 0; q < 16; q++)
        d_wi4[q * HH + j] = qpack4(wi[q], 8.0f, -8, 7);
    if (j < OO) {
        const float4* wo = (const float4*)(Wo + j * HH);
#pragma unroll
        for (int q = 0; q < 64; q++)
            d_wo4[j * 64 + q] = qpack4(wo[q], 8.0f, -8, 7);
    }
}

// ---------------------------------------------------------------------------
// Kernel 2: input projection u_int[b,t,j] = sum_i xq[b,t,i]*wiq[j,i]
// One CTA = (b, 64 timesteps). 256 threads; thread j computes u for column j.
// ---------------------------------------------------------------------------
__global__ void __launch_bounds__(256) proj_kernel(const float* __restrict__ X) {
    __shared__ int4 xs[64][4];  // 64 timesteps x 16 packed words (as int4)

    int b  = blockIdx.y;
    int t0 = blockIdx.x * 64;
    int j  = threadIdx.x;

    int wi[16];
#pragma unroll
    for (int q = 0; q < 16; q++) wi[q] = d_wi4[q * HH + j];

    // Cooperatively quantize+pack 64 timesteps of x into smem.
    {
        int tt = j >> 2, gw = j & 3;  // thread -> (timestep, 16-element group)
        const float4* xp =
            (const float4*)(X + (size_t)(b * TT + t0 + tt) * II + gw * 16);
        int4 pk;
        pk.x = qpack4(xp[0], 128.0f, -128, 127);
        pk.y = qpack4(xp[1], 128.0f, -128, 127);
        pk.z = qpack4(xp[2], 128.0f, -128, 127);
        pk.w = qpack4(xp[3], 128.0f, -128, 127);
        xs[tt][gw] = pk;
    }
    __syncthreads();

    int* up = d_u + (b * TT + t0) * HH + j;
#pragma unroll 4
    for (int tt = 0; tt < 64; tt++) {
        const int* xw = (const int*)xs[tt];
        int acc = 0;
#pragma unroll
        for (int q = 0; q < 16; q++) acc = __dp4a(xw[q], wi[q], acc);
        up[tt * HH] = acc;
    }
}

// ---------------------------------------------------------------------------
// Kernel 3: sequential recurrence + output head.
// One CTA per batch row. Thread j owns output column j and keeps Wr row j
// (64 packed words) in registers. h (256 int8) is double-buffered in smem;
// exactly one __syncthreads per step. u prefetched 4 steps ahead.
// ---------------------------------------------------------------------------
__global__ void __launch_bounds__(256, 2)
rnn_kernel(const float* __restrict__ bvec, float* __restrict__ out) {
    __shared__ int4 hs[2][16];  // two 256-byte h buffers

    int b = blockIdx.x;
    int j = threadIdx.x;

    int w[64];
#pragma unroll
    for (int q = 0; q < 64; q++) w[q] = d_wr4[q * HH + j];

    float bj = bvec[j];

    if (j < 32) ((int4*)hs)[j] = make_int4(0, 0, 0, 0);  // h0 = 0 (both buffers)
    __syncthreads();

    const int* up = d_u + b * TT * HH + j;
    int upf[4];
#pragma unroll
    for (int p = 0; p < 4; p++) upf[p] = up[p * HH];

#pragma unroll 4
    for (int t = 0; t < TT; t++) {
        int ucur = upf[t & 3];
        int tn = t + 4;
        if (tn > TT - 1) tn = TT - 1;
        upf[t & 3] = up[tn * HH];  // prefetch 4 steps ahead

        // z_int = u + h . wr_row(j)   (4 independent dp4a chains for ILP)
        int a0 = 0, a1 = 0, a2 = 0, a3 = 0;
        const int4* hp = hs[t & 1];
#pragma unroll
        for (int g = 0; g < 16; g++) {
            int4 hv = hp[g];
            a0 = __dp4a(hv.x, w[4 * g + 0], a0);
            a1 = __dp4a(hv.y, w[4 * g + 1], a1);
            a2 = __dp4a(hv.z, w[4 * g + 2], a2);
            a3 = __dp4a(hv.w, w[4 * g + 3], a3);
        }
        int z = ucur + ((a0 + a1) + (a2 + a3));

        // modReLU + 8-bit re-quantization (bit-exact vs reference)
        int az = z < 0 ? -z : z;
        float m = fmaxf((float)az * (1.0f / 1024.0f) + bj, 0.0f);
        int r = __float2int_rn(m * 128.0f);  // r >= 0, half-even
        int hq = (z > 0) ? (r < 127 ? r : 127)
                         : (z < 0 ? -(r < 128 ? r : 128) : 0);

        ((signed char*)hs[(t + 1) & 1])[j] = (signed char)hq;
        __syncthreads();
    }

    // Output head: out[b,o] = (h_last . woq_row(o)) / 1024. Final h is in hs[0]
    // (T even: step T-1 wrote buffer (T)&1 == 0).
    if (j < OO) {
        const int* hw = (const int*)hs[0];
        int acc = 0;
#pragma unroll
        for (int g = 0; g < 64; g++) acc = __dp4a(hw[g], d_wo4[j * 64 + g], acc);
        out[b * OO + j] = (float)acc * (1.0f / 1024.0f);
    }
}

// ---------------------------------------------------------------------------
extern "C" void kernel_launch(void* const* d_in, const int* in_sizes, int n_in,
                              void* d_out, int out_size) {
    const float* X  = (const float*)d_in[0];  // inputs [256,1024,64]
    const float* Wi = (const float*)d_in[1];  // [256,64]
    const float* Wr = (const float*)d_in[2];  // [256,256]
    const float* Wo = (const float*)d_in[3];  // [16,256]
    const float* bv = (const float*)d_in[4];  // [256]

    pack_weights_kernel<<<1, 256>>>(Wi, Wr, Wo);
    proj_kernel<<<dim3(TT / 64, BB), 256>>>(X);
    rnn_kernel<<<BB, 256>>>(bv, (float*)d_out);
}

// round 5
// speedup vs baseline: 1.0844x; 1.0844x over previous
#include <cuda_runtime.h>

// QORNN: B=256, T=1024, I=64, H=256, O=16
// Exact integer formulation (bit-exact vs the JAX fp32 reference):
//   xq  = clip(rint(x*128), -128, 127)              (int8)
//   wiq = clip(rint(Wi*8),  -8, 7)
//   wrq = clip(rint(Wr*8),  -8, 7)
//   woq = clip(rint(Wo*8),  -8, 7)
//   u_int[b,t,j] = sum_i xq*wiq                     (|.| <= 65536)
//   z_int = u_int + sum_k hq*wrq                    (|.| <= 327680 < 2^24)
//   m  = max(fma(z_int_abs, 1/1024, b[j]), 0)       (single fp32 rounding,
//                                                    == exact-div then add)
//   hq = sign(z)*clip(rint(m*128), ..)              in [-128,127]
//   out[b,o] = (sum_j hq*woq) / 1024

#define BB 256
#define TT 1024
#define II 64
#define HH 256
#define OO 16

// Scratch (allocation-free rule: __device__ globals)
__device__ int d_u[BB * TT * HH];   // 268 MB int32, u numerators
__device__ int d_wr4[64 * HH];      // [q][j]: packed wrq[j][4q..4q+3]
__device__ int d_wi4[16 * HH];      // [q][j]: packed wiq[j][4q..4q+3]
__device__ int d_wo4[OO * 64];      // [o][q]: packed woq[o][4q..4q+3]

__device__ __forceinline__ int clampi(int v, int lo, int hi) {
    return v < lo ? lo : (v > hi ? hi : v);
}

// Quantize 4 floats (round-half-even, clip) and pack into one dp4a word.
__device__ __forceinline__ int qpack4(float4 v, float s, int lo, int hi) {
    int a = clampi(__float2int_rn(v.x * s), lo, hi);
    int b = clampi(__float2int_rn(v.y * s), lo, hi);
    int c = clampi(__float2int_rn(v.z * s), lo, hi);
    int d = clampi(__float2int_rn(v.w * s), lo, hi);
    return (a & 255) | ((b & 255) << 8) | ((c & 255) << 16) | ((d & 255) << 24);
}

// ---------------------------------------------------------------------------
// Kernel 1: quantize + pack all weights. Grid = 256 CTAs (one per j-row),
// 64 threads each -> fully parallel, coalesced row reads.
// ---------------------------------------------------------------------------
__global__ void __launch_bounds__(64) pack_weights_kernel(
        const float* __restrict__ Wi,
        const float* __restrict__ Wr,
        const float* __restrict__ Wo) {
    int j = blockIdx.x;   // 0..255
    int q = threadIdx.x;  // 0..63

    const float4* wr = (const float4*)(Wr + j * HH);
    d_wr4[q * HH + j] = qpack4(wr[q], 8.0f, -8, 7);

    if (q < 16) {
        const float4* wi = (const float4*)(Wi + j * II);
        d_wi4[q * HH + j] = qpack4(wi[q], 8.0f, -8, 7);
    }
    if (j < OO) {
        const float4* wo = (const float4*)(Wo + j * HH);
        d_wo4[j * 64 + q] = qpack4(wo[q], 8.0f, -8, 7);
    }
}

// ---------------------------------------------------------------------------
// Kernel 2: input projection u_int[b,t,j] = sum_i xq[b,t,i]*wiq[j,i]
// One CTA = (b, 64 timesteps). 256 threads; thread j computes column j.
// ---------------------------------------------------------------------------
__global__ void __launch_bounds__(256) proj_kernel(const float* __restrict__ X) {
    __shared__ int4 xs[64][4];  // 64 timesteps x 16 packed words

    int b  = blockIdx.y;
    int t0 = blockIdx.x * 64;
    int j  = threadIdx.x;

    int wi[16];
#pragma unroll
    for (int q = 0; q < 16; q++) wi[q] = d_wi4[q * HH + j];

    // Cooperatively quantize+pack 64 timesteps of x into smem.
    {
        int tt = j >> 2, gw = j & 3;
        const float4* xp =
            (const float4*)(X + (size_t)(b * TT + t0 + tt) * II + gw * 16);
        int4 pk;
        pk.x = qpack4(xp[0], 128.0f, -128, 127);
        pk.y = qpack4(xp[1], 128.0f, -128, 127);
        pk.z = qpack4(xp[2], 128.0f, -128, 127);
        pk.w = qpack4(xp[3], 128.0f, -128, 127);
        xs[tt][gw] = pk;
    }
    __syncthreads();

    int* up = d_u + (b * TT + t0) * HH + j;
#pragma unroll 4
    for (int tt = 0; tt < 64; tt++) {
        const int* xw = (const int*)xs[tt];
        int acc = 0;
#pragma unroll
        for (int q = 0; q < 16; q++) acc = __dp4a(xw[q], wi[q], acc);
        up[tt * HH] = acc;
    }
}

// ---------------------------------------------------------------------------
// Kernel 3: sequential recurrence + output head.
// One CTA per batch row; thread j owns column j, Wr row j in 64 registers.
// h double-buffered in smem, one __syncthreads per step, u prefetched 4 ahead.
// CTAs bid>=148 (second co-resident on each doubled SM) start ~400 cycles
// late so their per-step epilogue/barrier tails overlap the partner CTA's
// dp4a bursts instead of phase-locking with them.
// ---------------------------------------------------------------------------
__global__ void __launch_bounds__(256, 2)
rnn_kernel(const float* __restrict__ bvec, float* __restrict__ out) {
    __shared__ int4 hs[2][16];   // two 256-byte h buffers
    __shared__ int  stagger_sink;

    int b = blockIdx.x;
    int j = threadIdx.x;

    int w[64];
#pragma unroll
    for (int q = 0; q < 64; q++) w[q] = d_wr4[q * HH + j];

    float bj = bvec[j];

    if (j < 32) ((int4*)hs)[j] = make_int4(0, 0, 0, 0);  // h0 = 0, both buffers

    if (b >= 148) {
        // ~400-cycle dependent-IMAD delay (anti-phase vs co-resident CTA).
        int x = j | 1;
#pragma unroll 1
        for (int i = 0; i < 96; i++) x = x * x + j;
        if (x == 13) stagger_sink = x;  // keep the chain alive; never read
    }
    __syncthreads();

    const int* up = d_u + b * TT * HH + j;
    int upf[4];
#pragma unroll
    for (int p = 0; p < 4; p++) upf[p] = up[p * HH];

#pragma unroll 4
    for (int t = 0; t < TT; t++) {
        int ucur = upf[t & 3];
        int tn = t + 4;
        if (tn > TT - 1) tn = TT - 1;
        upf[t & 3] = up[tn * HH];  // prefetch 4 steps ahead

        // z_int = u + h . wr_row(j): 8 independent dp4a chains (depth 8).
        const int4* hp = hs[t & 1];
        int a0 = 0, a1 = 0, a2 = 0, a3 = 0, a4 = 0, a5 = 0, a6 = 0, a7 = 0;
#pragma unroll
        for (int g = 0; g < 8; g++) {
            int4 h0 = hp[2 * g + 0];
            int4 h1 = hp[2 * g + 1];
            a0 = __dp4a(h0.x, w[8 * g + 0], a0);
            a1 = __dp4a(h0.y, w[8 * g + 1], a1);
            a2 = __dp4a(h0.z, w[8 * g + 2], a2);
            a3 = __dp4a(h0.w, w[8 * g + 3], a3);
            a4 = __dp4a(h1.x, w[8 * g + 4], a4);
            a5 = __dp4a(h1.y, w[8 * g + 5], a5);
            a6 = __dp4a(h1.z, w[8 * g + 6], a6);
            a7 = __dp4a(h1.w, w[8 * g + 7], a7);
        }
        int z = ucur + (((a0 + a1) + (a2 + a3)) + ((a4 + a5) + (a6 + a7)));

        // modReLU + 8-bit re-quantization (bit-exact vs reference):
        // az * 2^-10 is exact, so the fma has a single rounding == ref's add.
        int az = z < 0 ? -z : z;
        float m = fmaxf(fmaf((float)az, 1.0f / 1024.0f, bj), 0.0f);
        int r = __float2int_rn(m * 128.0f);  // r >= 0, half-even
        int hq = (z > 0) ? (r < 127 ? r : 127)
                         : (z < 0 ? -(r < 128 ? r : 128) : 0);

        ((signed char*)hs[(t + 1) & 1])[j] = (signed char)hq;
        __syncthreads();
    }

    // Output head: out[b,o] = (h_last . woq_row(o)) / 1024. Final h in hs[0]
    // (T even: step T-1 wrote buffer T&1 == 0).
    if (j < OO) {
        const int* hw = (const int*)hs[0];
        int acc = 0;
#pragma unroll
        for (int g = 0; g < 64; g++) acc = __dp4a(hw[g], d_wo4[j * 64 + g], acc);
        out[b * OO + j] = (float)acc * (1.0f / 1024.0f);
    }
}

// ---------------------------------------------------------------------------
extern "C" void kernel_launch(void* const* d_in, const int* in_sizes, int n_in,
                              void* d_out, int out_size) {
    const float* X  = (const float*)d_in[0];  // inputs [256,1024,64]
    const float* Wi = (const float*)d_in[1];  // [256,64]
    const float* Wr = (const float*)d_in[2];  // [256,256]
    const float* Wo = (const float*)d_in[3];  // [16,256]
    const float* bv = (const float*)d_in[4];  // [256]

    pack_weights_kernel<<<256, 64>>>(Wi, Wr, Wo);
    proj_kernel<<<dim3(TT / 64, BB), 256>>>(X);
    rnn_kernel<<<BB, 256>>>(bv, (float*)d_out);
}

// round 7
// speedup vs baseline: 1.1802x; 1.0883x over previous
#include <cuda_runtime.h>

// QORNN: B=256, T=1024, I=64, H=256, O=16
// Exact integer formulation (bit-exact vs the JAX fp32 reference):
//   xq  = clip(rint(x*128), -128, 127)              (int8)
//   wiq = clip(rint(Wi*8),  -8, 7)
//   wrq = clip(rint(Wr*8),  -8, 7)
//   woq = clip(rint(Wo*8),  -8, 7)
//   z_int = sum_i xq*wiq + sum_k hq*wrq             (|.| <= 327680 < 2^24)
//   m  = max(fma(|z|, 1/8, 128*b[j]), 0)            (== 128*ref-m, exact
//                                                    power-of-2 scaling
//                                                    commutes with RN)
//   hq = sign(z)*clip(rint(m), ..)                  in [-128,127]
//   out[b,o] = (sum_j hq*woq) / 1024
//
// The input projection is FUSED into the recurrence kernel: x[b,t,:] is
// prefetched 8 steps ahead into a smem ring and contributes 16 extra dp4a
// per thread per step, eliminating the 268MB u-scratch round trip and the
// standalone projection kernel.

#define BB 256
#define TT 1024
#define II 64
#define HH 256
#define OO 16

// Packed quantized weights (allocation-free rule: __device__ globals)
__device__ int d_wr4[64 * HH];      // [q][j]: packed wrq[j][4q..4q+3]
__device__ int d_wi4[16 * HH];      // [q][j]: packed wiq[j][4q..4q+3]
__device__ int d_wo4[OO * 64];      // [o][q]: packed woq[o][4q..4q+3]

__device__ __forceinline__ int clampi(int v, int lo, int hi) {
    return v < lo ? lo : (v > hi ? hi : v);
}

// Quantize 4 floats (round-half-even, clip) and pack into one dp4a word.
__device__ __forceinline__ int qpack4(float4 v, float s, int lo, int hi) {
    int a = clampi(__float2int_rn(v.x * s), lo, hi);
    int b = clampi(__float2int_rn(v.y * s), lo, hi);
    int c = clampi(__float2int_rn(v.z * s), lo, hi);
    int d = clampi(__float2int_rn(v.w * s), lo, hi);
    return (a & 255) | ((b & 255) << 8) | ((c & 255) << 16) | ((d & 255) << 24);
}

// ---------------------------------------------------------------------------
// Kernel 1: quantize + pack all weights. 256 CTAs x 64 threads.
// ---------------------------------------------------------------------------
__global__ void __launch_bounds__(64) pack_weights_kernel(
        const float* __restrict__ Wi,
        const float* __restrict__ Wr,
        const float* __restrict__ Wo) {
    int j = blockIdx.x;   // 0..255
    int q = threadIdx.x;  // 0..63

    const float4* wr = (const float4*)(Wr + j * HH);
    d_wr4[q * HH + j] = qpack4(wr[q], 8.0f, -8, 7);

    if (q < 16) {
        const float4* wi = (const float4*)(Wi + j * II);
        d_wi4[q * HH + j] = qpack4(wi[q], 8.0f, -8, 7);
    }
    if (j < OO) {
        const float4* wo = (const float4*)(Wo + j * HH);
        d_wo4[j * 64 + q] = qpack4(wo[q], 8.0f, -8, 7);
    }
}

// ---------------------------------------------------------------------------
// Kernel 2: fused projection + recurrence + output head.
// One CTA per batch row; thread j owns column j: Wr row j (64 words) and
// Wi row j (16 words) in registers. h double-buffered in smem (broadcast
// reads); x quantized into an 8-deep smem ring by threads j<64, 8 steps
// ahead of use. One __syncthreads per step.
// CTAs bid>=148 (second co-resident on a doubled SM) start ~400 cycles late
// so per-step tails interleave with the partner CTA's dp4a bursts.
// ---------------------------------------------------------------------------
__global__ void __launch_bounds__(256, 2)
rnn_kernel(const float* __restrict__ X, const float* __restrict__ bvec,
           float* __restrict__ out) {
    __shared__ int4 hs[2][16];    // two 256-byte h buffers
    __shared__ int4 xring[8][4];  // 8-step ring of packed xq (64 bytes/slot)
    __shared__ int  stagger_sink;

    int b = blockIdx.x;
    int j = threadIdx.x;

    int w[64];
#pragma unroll
    for (int q = 0; q < 64; q++) w[q] = d_wr4[q * HH + j];
    int wi[16];
#pragma unroll
    for (int q = 0; q < 16; q++) wi[q] = d_wi4[q * HH + j];

    float bj128 = bvec[j] * 128.0f;  // exact (|b|~0.03, power-of-2 scale)

    if (j < 32) ((int4*)hs)[j] = make_int4(0, 0, 0, 0);  // h0 = 0, both bufs

    // x prefetch prologue: fill ring slots 0..6 with xq(0..6); x(7) in rcur.
    const float* xp = X + (size_t)b * TT * II + j;  // column j of row b
    float rcur = 0.0f;
    if (j < II) {
        signed char* ring = (signed char*)xring;
#pragma unroll
        for (int p = 0; p < 7; p++) {
            int v = clampi(__float2int_rn(xp[p * II] * 128.0f), -128, 127);
            ring[p * 64 + j] = (signed char)v;
        }
        rcur = xp[7 * II];
    }

    if (b >= 148) {
        // ~400-cycle dependent-IMAD delay (anti-phase vs co-resident CTA).
        int x = j | 1;
#pragma unroll 1
        for (int i = 0; i < 96; i++) x = x * x + j;
        if (x == 13) stagger_sink = x;  // keep chain alive; never read
    }
    __syncthreads();

#pragma unroll 2
    for (int t = 0; t < TT; t++) {
        // x pipeline: quantize x(t+7) (loaded last step) into its ring slot,
        // issue the load for x(t+8). Writes target slot (t+7)&7 == (t-1)&7,
        // whose previous contents were last read at step t-1 (pre-barrier).
        if (j < II) {
            int tn = t + 8;
            if (tn > TT - 1) tn = TT - 1;
            float rnext = xp[tn * II];
            int v = clampi(__float2int_rn(rcur * 128.0f), -128, 127);
            ((signed char*)xring[(t + 7) & 7])[j] = (signed char)v;
            rcur = rnext;
        }

        // z = xq(t).wi_row(j) + h.wr_row(j): 8 independent dp4a chains.
        const int4* hp = hs[t & 1];
        const int4* xw = xring[t & 7];
        int a0 = 0, a1 = 0, a2 = 0, a3 = 0, a4 = 0, a5 = 0, a6 = 0, a7 = 0;
#pragma unroll
        for (int g = 0; g < 8; g++) {
            int4 h0 = hp[2 * g + 0];
            int4 h1 = hp[2 * g + 1];
            a0 = __dp4a(h0.x, w[8 * g + 0], a0);
            a1 = __dp4a(h0.y, w[8 * g + 1], a1);
            a2 = __dp4a(h0.z, w[8 * g + 2], a2);
            a3 = __dp4a(h0.w, w[8 * g + 3], a3);
            a4 = __dp4a(h1.x, w[8 * g + 4], a4);
            a5 = __dp4a(h1.y, w[8 * g + 5], a5);
            a6 = __dp4a(h1.z, w[8 * g + 6], a6);
            a7 = __dp4a(h1.w, w[8 * g + 7], a7);
        }
#pragma unroll
        for (int g = 0; g < 4; g++) {
            int4 xv = xw[g];
            a0 = __dp4a(xv.x, wi[4 * g + 0], a0);
            a1 = __dp4a(xv.y, wi[4 * g + 1], a1);
            a2 = __dp4a(xv.z, wi[4 * g + 2], a2);
            a3 = __dp4a(xv.w, wi[4 * g + 3], a3);
        }
        int z = (((a0 + a1) + (a2 + a3)) + ((a4 + a5) + (a6 + a7)));

        // modReLU + 8-bit re-quantization (bit-exact; see header note).
        int az = z < 0 ? -z : z;
        float m = fmaxf(fmaf((float)az, 0.125f, bj128), 0.0f);
        int r = __float2int_rn(m);  // r >= 0, half-even
        int hq = (z > 0) ? (r < 127 ? r : 127)
                         : (z < 0 ? -(r < 128 ? r : 128) : 0);

        ((signed char*)hs[(t + 1) & 1])[j] = (signed char)hq;
        __syncthreads();
    }

    // Output head: out[b,o] = (h_last . woq_row(o)) / 1024. Final h in hs[0]
    // (T even: step T-1 wrote buffer T&1 == 0).
    if (j < OO) {
        const int* hw = (const int*)hs[0];
        int acc = 0;
#pragma unroll
        for (int g = 0; g < 64; g++) acc = __dp4a(hw[g], d_wo4[j * 64 + g], acc);
        out[b * OO + j] = (float)acc * (1.0f / 1024.0f);
    }
}

// ---------------------------------------------------------------------------
extern "C" void kernel_launch(void* const* d_in, const int* in_sizes, int n_in,
                              void* d_out, int out_size) {
    const float* X  = (const float*)d_in[0];  // inputs [256,1024,64]
    const float* Wi = (const float*)d_in[1];  // [256,64]
    const float* Wr = (const float*)d_in[2];  // [256,256]
    const float* Wo = (const float*)d_in[3];  // [16,256]
    const float* bv = (const float*)d_in[4];  // [256]

    pack_weights_kernel<<<256, 64>>>(Wi, Wr, Wo);
    rnn_kernel<<<BB, 256>>>(X, bv, (float*)d_out);
}

// round 8
// speedup vs baseline: 1.3179x; 1.1167x over previous
#include <cuda_runtime.h>

// QORNN: B=256, T=1024, I=64, H=256, O=16
// Exact integer formulation (bit-exact vs the JAX fp32 reference):
//   xq  = clip(rint(x*128), -128, 127)              (int8)
//   wiq = clip(rint(Wi*8),  -8, 7)
//   wrq = clip(rint(Wr*8),  -8, 7)
//   woq = clip(rint(Wo*8),  -8, 7)
//   z_int = sum_i xq*wiq + sum_k hq*wrq             (|.| <= 327680 < 2^24)
//   m  = max(fma(|z|, 1/8, 128*b[j]), 0)            (== 128*ref-m; az*0.125
//                                                    is exact, single fp32
//                                                    rounding == reference)
//   hq = sign(z)*clip(rint(m), ..)                  in [-128,127]
//   out[b,o] = (sum_j hq*woq) / 1024
//
// Pipelining: x[b,t,:] is loaded 8 steps ahead into a smem ring, and the
// x-projection dot u(t+1) = xq(t+1).Wi_row(j) is computed during step t's
// epilogue (it is h-independent), carried across the barrier in a register.
// This fills the otherwise-dead issue slots of the serial modReLU chain.

#define BB 256
#define TT 1024
#define II 64
#define HH 256
#define OO 16

// Packed quantized weights (allocation-free rule: __device__ globals)
__device__ int d_wr4[64 * HH];      // [q][j]: packed wrq[j][4q..4q+3]
__device__ int d_wi4[16 * HH];      // [q][j]: packed wiq[j][4q..4q+3]
__device__ int d_wo4[OO * 64];      // [o][q]: packed woq[o][4q..4q+3]

__device__ __forceinline__ int clampi(int v, int lo, int hi) {
    return v < lo ? lo : (v > hi ? hi : v);
}

// Quantize 4 floats (round-half-even, clip) and pack into one dp4a word.
__device__ __forceinline__ int qpack4(float4 v, float s, int lo, int hi) {
    int a = clampi(__float2int_rn(v.x * s), lo, hi);
    int b = clampi(__float2int_rn(v.y * s), lo, hi);
    int c = clampi(__float2int_rn(v.z * s), lo, hi);
    int d = clampi(__float2int_rn(v.w * s), lo, hi);
    return (a & 255) | ((b & 255) << 8) | ((c & 255) << 16) | ((d & 255) << 24);
}

// ---------------------------------------------------------------------------
// Kernel 1: quantize + pack all weights. 256 CTAs x 64 threads.
// ---------------------------------------------------------------------------
__global__ void __launch_bounds__(64) pack_weights_kernel(
        const float* __restrict__ Wi,
        const float* __restrict__ Wr,
        const float* __restrict__ Wo) {
    int j = blockIdx.x;   // 0..255
    int q = threadIdx.x;  // 0..63

    const float4* wr = (const float4*)(Wr + j * HH);
    d_wr4[q * HH + j] = qpack4(wr[q], 8.0f, -8, 7);

    if (q < 16) {
        const float4* wi = (const float4*)(Wi + j * II);
        d_wi4[q * HH + j] = qpack4(wi[q], 8.0f, -8, 7);
    }
    if (j < OO) {
        const float4* wo = (const float4*)(Wo + j * HH);
        d_wo4[j * 64 + q] = qpack4(wo[q], 8.0f, -8, 7);
    }
}

// ---------------------------------------------------------------------------
// Kernel 2: fused projection + recurrence + output head.
// One CTA per batch row; thread j owns column j (Wr row j: 64 regs, Wi row
// j: 16 regs). h double-buffered in smem; x quantized into an 8-deep smem
// ring by threads j<64. One __syncthreads per step.
// ---------------------------------------------------------------------------
__global__ void __launch_bounds__(256, 2)
rnn_kernel(const float* __restrict__ X, const float* __restrict__ bvec,
           float* __restrict__ out) {
    __shared__ int4 hs[2][16];    // two 256-byte h buffers
    __shared__ int4 xring[8][4];  // 8-step ring of packed xq (64 bytes/slot)
    __shared__ int  stagger_sink;

    int b = blockIdx.x;
    int j = threadIdx.x;

    int w[64];
#pragma unroll
    for (int q = 0; q < 64; q++) w[q] = d_wr4[q * HH + j];
    int wi[16];
#pragma unroll
    for (int q = 0; q < 16; q++) wi[q] = d_wi4[q * HH + j];

    float bj128 = bvec[j] * 128.0f;  // exact (|b|~0.03, power-of-2 scale)

    if (j < 32) ((int4*)hs)[j] = make_int4(0, 0, 0, 0);  // h0 = 0, both bufs

    // x prefetch prologue: ring slots 0..6 <- xq(0..6); x(7) in rcur.
    const float* xp = X + (size_t)b * TT * II + j;  // column j of row b
    float rcur = 0.0f;
    if (j < II) {
        signed char* ring = (signed char*)xring;
#pragma unroll
        for (int p = 0; p < 7; p++) {
            int v = clampi(__float2int_rn(xp[p * II] * 128.0f), -128, 127);
            ring[p * 64 + j] = (signed char)v;
        }
        rcur = xp[7 * II];
    }

    if (b >= 148) {
        // ~400-cycle dependent-IMAD delay: anti-phase vs co-resident CTA so
        // the two CTAs' epilogue/barrier tails interleave with dp4a bursts.
        int x = j | 1;
#pragma unroll 1
        for (int i = 0; i < 96; i++) x = x * x + j;
        if (x == 13) stagger_sink = x;  // keep chain alive; never read
    }
    __syncthreads();

    // u(0) = xq(0) . wi_row(j)
    int uacc;
    {
        const int4* xw = xring[0];
        int c0 = 0, c1 = 0, c2 = 0, c3 = 0;
#pragma unroll
        for (int g = 0; g < 4; g++) {
            int4 xv = xw[g];
            c0 = __dp4a(xv.x, wi[4 * g + 0], c0);
            c1 = __dp4a(xv.y, wi[4 * g + 1], c1);
            c2 = __dp4a(xv.z, wi[4 * g + 2], c2);
            c3 = __dp4a(xv.w, wi[4 * g + 3], c3);
        }
        uacc = (c0 + c1) + (c2 + c3);
    }

#pragma unroll 1
    for (int tb = 0; tb < TT; tb += 8) {
#pragma unroll
        for (int uu = 0; uu < 8; uu++) {
            int t = tb + uu;

            // ---- h-dot for step t: 64 dp4a, 8 independent chains ----
            const int4* hp = hs[uu & 1];
            int a0 = 0, a1 = 0, a2 = 0, a3 = 0, a4 = 0, a5 = 0, a6 = 0, a7 = 0;
#pragma unroll
            for (int g = 0; g < 8; g++) {
                int4 h0 = hp[2 * g + 0];
                int4 h1 = hp[2 * g + 1];
                a0 = __dp4a(h0.x, w[8 * g + 0], a0);
                a1 = __dp4a(h0.y, w[8 * g + 1], a1);
                a2 = __dp4a(h0.z, w[8 * g + 2], a2);
                a3 = __dp4a(h0.w, w[8 * g + 3], a3);
                a4 = __dp4a(h1.x, w[8 * g + 4], a4);
                a5 = __dp4a(h1.y, w[8 * g + 5], a5);
                a6 = __dp4a(h1.z, w[8 * g + 6], a6);
                a7 = __dp4a(h1.w, w[8 * g + 7], a7);
            }
            int z = uacc +
                    ((((a0 + a1) + (a2 + a3)) + ((a4 + a5) + (a6 + a7))));

            // ---- x pipeline (h-independent; fills the epilogue window) ----
            // quantize x(t+7) (loaded last step) into ring slot (t+7)&7,
            // issue load of x(t+8).
            if (j < II) {
                int tn = t + 8;
                if (tn > TT - 1) tn = TT - 1;
                float rnext = xp[tn * II];
                int v = clampi(__float2int_rn(rcur * 128.0f), -128, 127);
                ((signed char*)xring[(uu + 7) & 7])[j] = (signed char)v;
                rcur = rnext;
            }
            // u(t+1) from ring slot (t+1)&7 (written >= 6 barriers ago).
            {
                const int4* xw = xring[(uu + 1) & 7];
                int c0 = 0, c1 = 0, c2 = 0, c3 = 0;
#pragma unroll
                for (int g = 0; g < 4; g++) {
                    int4 xv = xw[g];
                    c0 = __dp4a(xv.x, wi[4 * g + 0], c0);
                    c1 = __dp4a(xv.y, wi[4 * g + 1], c1);
                    c2 = __dp4a(xv.z, wi[4 * g + 2], c2);
                    c3 = __dp4a(xv.w, wi[4 * g + 3], c3);
                }
                uacc = (c0 + c1) + (c2 + c3);
            }

            // ---- modReLU + 8-bit requantization (bit-exact) ----
            int az = z < 0 ? -z : z;
            float m = fmaxf(fmaf((float)az, 0.125f, bj128), 0.0f);
            m = fminf(m, 128.0f);            // negative-side cap; fma pipe
            int r = __float2int_rn(m);       // r >= 0, half-even
            int rp = r < 127 ? r : 127;      // positive-side cap
            int hq = (z > 0) ? rp : (z < 0 ? -r : 0);

            ((signed char*)hs[(uu + 1) & 1])[j] = (signed char)hq;
            __syncthreads();
        }
    }

    // Output head: out[b,o] = (h_last . woq_row(o)) / 1024. Final h in hs[0]
    // (T even: step T-1 wrote buffer T&1 == 0).
    if (j < OO) {
        const int* hw = (const int*)hs[0];
        int acc = 0;
#pragma unroll
        for (int g = 0; g < 64; g++) acc = __dp4a(hw[g], d_wo4[j * 64 + g], acc);
        out[b * OO + j] = (float)acc * (1.0f / 1024.0f);
    }
}

// ---------------------------------------------------------------------------
extern "C" void kernel_launch(void* const* d_in, const int* in_sizes, int n_in,
                              void* d_out, int out_size) {
    const float* X  = (const float*)d_in[0];  // inputs [256,1024,64]
    const float* Wi = (const float*)d_in[1];  // [256,64]
    const float* Wr = (const float*)d_in[2];  // [256,256]
    const float* Wo = (const float*)d_in[3];  // [16,256]
    const float* bv = (const float*)d_in[4];  // [256]

    pack_weights_kernel<<<256, 64>>>(Wi, Wr, Wo);
    rnn_kernel<<<BB, 256>>>(X, bv, (float*)d_out);
}